// round 5
// baseline (speedup 1.0000x reference)
#include <cuda_runtime.h>
#include <cuda_fp16.h>
#include <cstdint>
#include <math.h>

#define BB 4
#define TT 2048
#define CC 1024
#define NH 16
#define HD 64
#define M1 (BB*TT)          // 8192
#define N_QKV (3*CC)        // 3072

// ---------------------------------------------------------------------------
// Device-global scratch. fp16 2-pass split: A-side hi+lo, B-side hi only.
// ---------------------------------------------------------------------------
__device__ __half g_xhi[M1*CC], g_xlo[M1*CC];
__device__ __half g_wqh[N_QKV*CC];
__device__ __half g_wph[CC*CC];
__device__ __half g_qh[BB*NH*TT*HD], g_ql[BB*NH*TT*HD];
__device__ __half g_kh[BB*NH*TT*HD];
__device__ __half g_vh[BB*NH*TT*HD];
__device__ __half g_ahi[M1*CC], g_alo[M1*CC];

// ---------------------------------------------------------------------------
// PTX helpers
// ---------------------------------------------------------------------------
__device__ __forceinline__ uint32_t smem_u32(const void* p) {
    uint32_t a;
    asm("{ .reg .u64 t; cvta.to.shared.u64 t, %1; cvt.u32.u64 %0, t; }"
        : "=r"(a) : "l"(p));
    return a;
}
__device__ __forceinline__ void cpasync16(uint32_t dst, const void* src) {
    asm volatile("cp.async.cg.shared.global [%0], [%1], 16;"
                 :: "r"(dst), "l"(src) : "memory");
}
#define CP_COMMIT() asm volatile("cp.async.commit_group;" ::: "memory")
#define CP_WAIT(N)  asm volatile("cp.async.wait_group %0;" :: "n"(N) : "memory")

__device__ __forceinline__ void ldsm4(uint32_t& r0, uint32_t& r1, uint32_t& r2,
                                      uint32_t& r3, uint32_t a) {
    asm volatile("ldmatrix.sync.aligned.m8n8.x4.shared.b16 {%0,%1,%2,%3},[%4];"
                 : "=r"(r0), "=r"(r1), "=r"(r2), "=r"(r3) : "r"(a));
}
__device__ __forceinline__ void ldsm4t(uint32_t& r0, uint32_t& r1, uint32_t& r2,
                                       uint32_t& r3, uint32_t a) {
    asm volatile("ldmatrix.sync.aligned.m8n8.x4.trans.shared.b16 {%0,%1,%2,%3},[%4];"
                 : "=r"(r0), "=r"(r1), "=r"(r2), "=r"(r3) : "r"(a));
}
__device__ __forceinline__ void mma16816(float* c, const uint32_t* a,
                                         uint32_t b0, uint32_t b1) {
    asm volatile("mma.sync.aligned.m16n8k16.row.col.f32.f16.f16.f32 "
                 "{%0,%1,%2,%3},{%4,%5,%6,%7},{%8,%9},{%0,%1,%2,%3};"
                 : "+f"(c[0]), "+f"(c[1]), "+f"(c[2]), "+f"(c[3])
                 : "r"(a[0]), "r"(a[1]), "r"(a[2]), "r"(a[3]), "r"(b0), "r"(b1));
}

__device__ __forceinline__ void split_pair(float x0, float x1,
                                           uint32_t& hi, uint32_t& lo) {
    __half h0 = __float2half(x0), h1 = __float2half(x1);
    __half2 hp = __halves2half2(h0, h1);
    __half2 lp = __halves2half2(__float2half(x0 - __half2float(h0)),
                                __float2half(x1 - __half2float(h1)));
    hi = *(uint32_t*)&hp;
    lo = *(uint32_t*)&lp;
}
__device__ __forceinline__ void split_store(__half* dh, __half* dl,
                                            size_t off, float v0, float v1) {
    uint32_t hi, lo;
    split_pair(v0, v1, hi, lo);
    *(uint32_t*)(dh + off) = hi;
    *(uint32_t*)(dl + off) = lo;
}
__device__ __forceinline__ void hi_store(__half* dh, size_t off, float v0, float v1) {
    __half2 hp = __halves2half2(__float2half(v0), __float2half(v1));
    *(uint32_t*)(dh + off) = *(uint32_t*)&hp;
}

// ---------------------------------------------------------------------------
__global__ __launch_bounds__(256) void convert_x(const float* __restrict__ src)
{
    int i = blockIdx.x * 256 + threadIdx.x;
    float4 v = ((const float4*)src)[i];
    split_store(g_xhi, g_xlo, (size_t)i * 4,     v.x, v.y);
    split_store(g_xhi, g_xlo, (size_t)i * 4 + 2, v.z, v.w);
}

template<int W>
__global__ void transpose_w(const float* __restrict__ w)
{
    __half* th = (W == 0) ? g_wqh : g_wph;
    const int N = (W == 0) ? N_QKV : CC;
    __shared__ float ts[32][33];
    int n0 = blockIdx.x * 32, k0 = blockIdx.y * 32;
    int tx = threadIdx.x, ty = threadIdx.y;
    #pragma unroll
    for (int i = 0; i < 32; i += 8)
        ts[ty + i][tx] = w[(size_t)(k0 + ty + i) * N + n0 + tx];
    __syncthreads();
    #pragma unroll
    for (int i = 0; i < 32; i += 8)
        th[(size_t)(n0 + ty + i) * CC + k0 + tx] = __float2half(ts[tx][ty + i]);
}

// ---------------------------------------------------------------------------
// GEMM: C[128x128] = A[M,1024] @ B^T + bias. fp16 2-pass, fp32 accum.
// 3-stage cp.async, ONE __syncthreads per K-iter, hi-sweep then lo-sweep.
// ---------------------------------------------------------------------------
#define GST 30720
#define GSMEM (3*GST)

template<int EPI>
__global__ __launch_bounds__(256, 2) void mma_gemm(const float* __restrict__ bias,
                                                   float* __restrict__ outp)
{
    const __half* Ahi = (EPI == 0) ? g_xhi : g_ahi;
    const __half* Alo = (EPI == 0) ? g_xlo : g_alo;
    const __half* Bhi = (EPI == 0) ? g_wqh : g_wph;

    extern __shared__ char smc[];
    const uint32_t smb = smem_u32(smc);
    const int t = threadIdx.x, wid = t >> 5, l = t & 31;
    const int wm = wid >> 2, wn = wid & 3;
    const int n0 = blockIdx.x * 128, m0 = blockIdx.y * 128;

    float acc[4][4][4];
    #pragma unroll
    for (int i = 0; i < 4; i++)
        #pragma unroll
        for (int j = 0; j < 4; j++)
            #pragma unroll
            for (int k = 0; k < 4; k++) acc[i][j][k] = 0.f;

    auto issue = [&](int s) {
        const int koff = s * 32;
        const uint32_t sb = smb + (s % 3) * GST;
        #pragma unroll
        for (int i = 0; i < 2; i++) {
            int c = 2 * t + i, row = c >> 2, q = c & 3;
            uint32_t so = (uint32_t)(row * 80 + q * 16);
            size_t ga = (size_t)(m0 + row) * CC + koff + q * 8;
            size_t gb = (size_t)(n0 + row) * CC + koff + q * 8;
            cpasync16(sb + so,         Ahi + ga);
            cpasync16(sb + 10240 + so, Alo + ga);
            cpasync16(sb + 20480 + so, Bhi + gb);
        }
        CP_COMMIT();
    };

    issue(0);
    issue(1);
    for (int s = 0; s < 32; s++) {
        if (s < 30) CP_WAIT(1);
        else        CP_WAIT(0);
        __syncthreads();
        if (s + 2 < 32) issue(s + 2);
        const uint32_t sb = smb + (s % 3) * GST;
        #pragma unroll
        for (int ks = 0; ks < 2; ks++) {
            uint32_t ah[4][4], al[4][4];
            #pragma unroll
            for (int mt = 0; mt < 4; mt++) {
                uint32_t ad = sb + (uint32_t)((wm * 64 + mt * 16 + (l & 15)) * 80
                                              + ks * 32 + (l >> 4) * 16);
                ldsm4(ah[mt][0], ah[mt][1], ah[mt][2], ah[mt][3], ad);
                ldsm4(al[mt][0], al[mt][1], al[mt][2], al[mt][3], ad + 10240);
            }
            uint32_t bh[4][2];
            #pragma unroll
            for (int j = 0; j < 2; j++) {
                uint32_t bd = sb + 20480
                    + (uint32_t)((wn * 32 + 16 * j + (l & 7) + ((l >> 4) & 1) * 8) * 80
                                 + ks * 32 + ((l >> 3) & 1) * 16);
                uint32_t r0, r1, r2, r3;
                ldsm4(r0, r1, r2, r3, bd);
                bh[2*j][0] = r0; bh[2*j][1] = r1; bh[2*j+1][0] = r2; bh[2*j+1][1] = r3;
            }
            // hi sweep (16 independent accums), then lo sweep
            #pragma unroll
            for (int mt = 0; mt < 4; mt++)
                #pragma unroll
                for (int nt = 0; nt < 4; nt++)
                    mma16816(acc[mt][nt], ah[mt], bh[nt][0], bh[nt][1]);
            #pragma unroll
            for (int mt = 0; mt < 4; mt++)
                #pragma unroll
                for (int nt = 0; nt < 4; nt++)
                    mma16816(acc[mt][nt], al[mt], bh[nt][0], bh[nt][1]);
        }
    }

    #pragma unroll
    for (int mt = 0; mt < 4; mt++) {
        const int rA = m0 + wm * 64 + mt * 16 + (l >> 2);
        const int rB = rA + 8;
        #pragma unroll
        for (int nt = 0; nt < 4; nt++) {
            const int n = n0 + wn * 32 + nt * 8 + 2 * (l & 3);
            const float bi0 = bias[n], bi1 = bias[n + 1];
            float v0 = acc[mt][nt][0] + bi0, v1 = acc[mt][nt][1] + bi1;
            float v2 = acc[mt][nt][2] + bi0, v3 = acc[mt][nt][3] + bi1;
            if (EPI == 0) {
                const int which = n >> 10;
                const int h = (n & 1023) >> 6, d = n & 63;
                const int bA = rA >> 11, tA = rA & 2047;
                const int bB = rB >> 11, tB = rB & 2047;
                const size_t oA = (((size_t)(bA * NH + h)) * TT + tA) * HD + d;
                const size_t oB = (((size_t)(bB * NH + h)) * TT + tB) * HD + d;
                if (which == 0) {
                    split_store(g_qh, g_ql, oA, v0 * 0.125f, v1 * 0.125f);
                    split_store(g_qh, g_ql, oB, v2 * 0.125f, v3 * 0.125f);
                } else if (which == 1) {
                    hi_store(g_kh, oA, v0, v1);
                    hi_store(g_kh, oB, v2, v3);
                } else {
                    hi_store(g_vh, oA, v0, v1);
                    hi_store(g_vh, oB, v2, v3);
                }
            } else {
                *(float2*)&outp[(size_t)rA * CC + n] = make_float2(v0, v1);
                *(float2*)&outp[(size_t)rB * CC + n] = make_float2(v2, v3);
            }
        }
    }
}

// ---------------------------------------------------------------------------
// Flash attention (fp16 2-pass). 256 thr / 8 warps, 128-row q tile, 64-col KV.
// smem: Qh@0 (18432) Ql@18432 | 3 KV stages @36864 + stg*18432 (Kh, Vh@+9216)
// ONE __syncthreads per KV tile.
// ---------------------------------------------------------------------------
#define FQ_SZ 18432
#define FKV_OFF 36864
#define FKV_ST 18432
#define FLASH_SMEM (FKV_OFF + 3*FKV_ST)   // 92160

__global__ __launch_bounds__(256, 2) void flash_mma()
{
    extern __shared__ char smc[];
    const uint32_t smb = smem_u32(smc);
    const int t = threadIdx.x, w = t >> 5, l = t & 31;
    const int qt = (int)gridDim.x - 1 - (int)blockIdx.x;   // heavy tiles first
    const int h = blockIdx.y, b = blockIdx.z;
    const size_t hoff = ((size_t)(b * NH + h)) * TT * HD;
    const int q0 = qt * 128;
    const int nk = 2 * qt + 2;            // 64-col KV tiles

    auto kvload = [&](int kt) {
        const uint32_t sb = smb + FKV_OFF + (kt % 3) * FKV_ST;
        const int k0 = kt * 64;
        #pragma unroll
        for (int i = 0; i < 2; i++) {
            int c = t + i * 256, row = c >> 3, q = c & 7;
            uint32_t so = (uint32_t)(row * 144 + q * 16);
            size_t g = hoff + (size_t)(k0 + row) * HD + q * 8;
            cpasync16(sb + so,        g_kh + g);
            cpasync16(sb + 9216 + so, g_vh + g);
        }
        CP_COMMIT();
    };

    // Q (128 rows hi+lo) + KV tile 0 share group 0; KV tile 1 = group 1
    #pragma unroll
    for (int i = 0; i < 4; i++) {
        int c = t + i * 256, row = c >> 3, q = c & 7;
        uint32_t so = (uint32_t)(row * 144 + q * 16);
        size_t g = hoff + (size_t)(q0 + row) * HD + q * 8;
        cpasync16(smb + so,         g_qh + g);
        cpasync16(smb + FQ_SZ + so, g_ql + g);
    }
    kvload(0);
    kvload(1);

    float mA = -1e30f, mB = -1e30f, lA = 0.f, lB = 0.f;
    float o[8][4];
    #pragma unroll
    for (int j = 0; j < 8; j++)
        #pragma unroll
        for (int k = 0; k < 4; k++) o[j][k] = 0.f;

    uint32_t qh[4][4], ql[4][4];

    for (int kt = 0; kt < nk; kt++) {
        if (kt < nk - 1) CP_WAIT(1);
        else             CP_WAIT(0);
        __syncthreads();
        if (kt + 2 < nk) kvload(kt + 2);
        if (kt == 0) {
            #pragma unroll
            for (int ks = 0; ks < 4; ks++) {
                uint32_t ad = smb + (uint32_t)((w * 16 + (l & 15)) * 144
                                               + ks * 32 + (l >> 4) * 16);
                ldsm4(qh[ks][0], qh[ks][1], qh[ks][2], qh[ks][3], ad);
                ldsm4(ql[ks][0], ql[ks][1], ql[ks][2], ql[ks][3], ad + FQ_SZ);
            }
        }
        const uint32_t sb = smb + FKV_OFF + (kt % 3) * FKV_ST;

        // S = Q K^T (2-pass)
        float s[8][4];
        #pragma unroll
        for (int j = 0; j < 8; j++)
            #pragma unroll
            for (int k = 0; k < 4; k++) s[j][k] = 0.f;
        #pragma unroll
        for (int ks = 0; ks < 4; ks++) {
            #pragma unroll
            for (int j = 0; j < 4; j++) {
                uint32_t kd = sb + (uint32_t)((16 * j + (l & 7) + ((l >> 4) & 1) * 8) * 144
                                              + ks * 32 + ((l >> 3) & 1) * 16);
                uint32_t r0, r1, r2, r3;
                ldsm4(r0, r1, r2, r3, kd);
                mma16816(s[2*j],   qh[ks], r0, r1);
                mma16816(s[2*j+1], qh[ks], r2, r3);
                mma16816(s[2*j],   ql[ks], r0, r1);
                mma16816(s[2*j+1], ql[ks], r2, r3);
            }
        }

        const int rA = q0 + w * 16 + (l >> 2), rB = rA + 8;
        if (kt >= 2 * qt) {
            const int cb = 2 * (l & 3);
            #pragma unroll
            for (int j = 0; j < 8; j++) {
                int cg = kt * 64 + 8 * j + cb;
                if (cg     > rA) s[j][0] = -1e30f;
                if (cg + 1 > rA) s[j][1] = -1e30f;
                if (cg     > rB) s[j][2] = -1e30f;
                if (cg + 1 > rB) s[j][3] = -1e30f;
            }
        }

        // online softmax
        float mxA = -1e30f, mxB = -1e30f;
        #pragma unroll
        for (int j = 0; j < 8; j++) {
            mxA = fmaxf(mxA, fmaxf(s[j][0], s[j][1]));
            mxB = fmaxf(mxB, fmaxf(s[j][2], s[j][3]));
        }
        mxA = fmaxf(mxA, __shfl_xor_sync(0xffffffffu, mxA, 1));
        mxA = fmaxf(mxA, __shfl_xor_sync(0xffffffffu, mxA, 2));
        mxB = fmaxf(mxB, __shfl_xor_sync(0xffffffffu, mxB, 1));
        mxB = fmaxf(mxB, __shfl_xor_sync(0xffffffffu, mxB, 2));
        const float nmA = fmaxf(mA, mxA), nmB = fmaxf(mB, mxB);
        const float aA = __expf(mA - nmA), aB = __expf(mB - nmB);
        mA = nmA; mB = nmB;
        float suA = 0.f, suB = 0.f;
        #pragma unroll
        for (int j = 0; j < 8; j++) {
            s[j][0] = __expf(s[j][0] - mA);
            s[j][1] = __expf(s[j][1] - mA);
            s[j][2] = __expf(s[j][2] - mB);
            s[j][3] = __expf(s[j][3] - mB);
            suA += s[j][0] + s[j][1];
            suB += s[j][2] + s[j][3];
        }
        suA += __shfl_xor_sync(0xffffffffu, suA, 1);
        suA += __shfl_xor_sync(0xffffffffu, suA, 2);
        suB += __shfl_xor_sync(0xffffffffu, suB, 1);
        suB += __shfl_xor_sync(0xffffffffu, suB, 2);
        lA = lA * aA + suA;
        lB = lB * aB + suB;
        #pragma unroll
        for (int j = 0; j < 8; j++) {
            o[j][0] *= aA; o[j][1] *= aA; o[j][2] *= aB; o[j][3] *= aB;
        }

        // O += P V (2-pass; V via ldmatrix.trans)
        #pragma unroll
        for (int ks = 0; ks < 4; ks++) {
            uint32_t pa[4], pb[4];
            split_pair(s[2*ks][0],   s[2*ks][1],   pa[0], pb[0]);
            split_pair(s[2*ks][2],   s[2*ks][3],   pa[1], pb[1]);
            split_pair(s[2*ks+1][0], s[2*ks+1][1], pa[2], pb[2]);
            split_pair(s[2*ks+1][2], s[2*ks+1][3], pa[3], pb[3]);
            #pragma unroll
            for (int j = 0; j < 4; j++) {
                uint32_t vd = sb + 9216
                    + (uint32_t)((ks * 16 + (l & 7) + ((l >> 3) & 1) * 8) * 144
                                 + 32 * j + ((l >> 4) & 1) * 16);
                uint32_t r0, r1, r2, r3;
                ldsm4t(r0, r1, r2, r3, vd);
                mma16816(o[2*j],   pa, r0, r1);
                mma16816(o[2*j+1], pa, r2, r3);
                mma16816(o[2*j],   pb, r0, r1);
                mma16816(o[2*j+1], pb, r2, r3);
            }
        }
    }

    const float iA = 1.f / lA, iB = 1.f / lB;
    const int rA = q0 + w * 16 + (l >> 2), rB = rA + 8;
    const size_t baseA = ((size_t)(b * TT + rA)) * CC + h * HD;
    const size_t baseB = ((size_t)(b * TT + rB)) * CC + h * HD;
    #pragma unroll
    for (int j = 0; j < 8; j++) {
        const int d = 8 * j + 2 * (l & 3);
        split_store(g_ahi, g_alo, baseA + d, o[j][0] * iA, o[j][1] * iA);
        split_store(g_ahi, g_alo, baseB + d, o[j][2] * iB, o[j][3] * iB);
    }
}

// ---------------------------------------------------------------------------
extern "C" void kernel_launch(void* const* d_in, const int* in_sizes, int n_in,
                              void* d_out, int out_size)
{
    const float* x      = (const float*)d_in[0];
    const float* w_attn = (const float*)d_in[1];
    const float* b_attn = (const float*)d_in[2];
    const float* w_proj = (const float*)d_in[3];
    const float* b_proj = (const float*)d_in[4];
    float* out = (float*)d_out;

    cudaFuncSetAttribute(mma_gemm<0>, cudaFuncAttributeMaxDynamicSharedMemorySize, GSMEM);
    cudaFuncSetAttribute(mma_gemm<1>, cudaFuncAttributeMaxDynamicSharedMemorySize, GSMEM);
    cudaFuncSetAttribute(flash_mma, cudaFuncAttributeMaxDynamicSharedMemorySize, FLASH_SMEM);

    convert_x<<<M1 * CC / 1024, 256>>>(x);
    transpose_w<0><<<dim3(N_QKV / 32, CC / 32), dim3(32, 8)>>>(w_attn);
    transpose_w<1><<<dim3(CC / 32, CC / 32), dim3(32, 8)>>>(w_proj);

    mma_gemm<0><<<dim3(N_QKV / 128, M1 / 128), 256, GSMEM>>>(b_attn, nullptr);
    flash_mma<<<dim3(TT / 128, NH, BB), 256, FLASH_SMEM>>>();
    mma_gemm<1><<<dim3(CC / 128, M1 / 128), 256, GSMEM>>>(b_proj, out);
}

// round 6
// speedup vs baseline: 1.6624x; 1.6624x over previous
#include <cuda_runtime.h>
#include <cuda_fp16.h>
#include <cstdint>
#include <math.h>

#define BB 4
#define TT 2048
#define CC 1024
#define NH 16
#define HD 64
#define M1 (BB*TT)          // 8192
#define N_QKV (3*CC)        // 3072

// ---------------------------------------------------------------------------
// Device-global scratch: pure fp16 (1-pass) operands.
// ---------------------------------------------------------------------------
__device__ __half g_xh[M1*CC];
__device__ __half g_wqh[N_QKV*CC];
__device__ __half g_wph[CC*CC];
__device__ __half g_qh[BB*NH*TT*HD];
__device__ __half g_kh[BB*NH*TT*HD];
__device__ __half g_vh[BB*NH*TT*HD];
__device__ __half g_ah[M1*CC];

// ---------------------------------------------------------------------------
// PTX helpers
// ---------------------------------------------------------------------------
__device__ __forceinline__ uint32_t smem_u32(const void* p) {
    uint32_t a;
    asm("{ .reg .u64 t; cvta.to.shared.u64 t, %1; cvt.u32.u64 %0, t; }"
        : "=r"(a) : "l"(p));
    return a;
}
__device__ __forceinline__ void cpasync16(uint32_t dst, const void* src) {
    asm volatile("cp.async.cg.shared.global [%0], [%1], 16;"
                 :: "r"(dst), "l"(src) : "memory");
}
#define CP_COMMIT() asm volatile("cp.async.commit_group;" ::: "memory")
#define CP_WAIT(N)  asm volatile("cp.async.wait_group %0;" :: "n"(N) : "memory")

__device__ __forceinline__ void ldsm4(uint32_t& r0, uint32_t& r1, uint32_t& r2,
                                      uint32_t& r3, uint32_t a) {
    asm volatile("ldmatrix.sync.aligned.m8n8.x4.shared.b16 {%0,%1,%2,%3},[%4];"
                 : "=r"(r0), "=r"(r1), "=r"(r2), "=r"(r3) : "r"(a));
}
__device__ __forceinline__ void ldsm4t(uint32_t& r0, uint32_t& r1, uint32_t& r2,
                                       uint32_t& r3, uint32_t a) {
    asm volatile("ldmatrix.sync.aligned.m8n8.x4.trans.shared.b16 {%0,%1,%2,%3},[%4];"
                 : "=r"(r0), "=r"(r1), "=r"(r2), "=r"(r3) : "r"(a));
}
__device__ __forceinline__ void mma16816(float* c, const uint32_t* a,
                                         uint32_t b0, uint32_t b1) {
    asm volatile("mma.sync.aligned.m16n8k16.row.col.f32.f16.f16.f32 "
                 "{%0,%1,%2,%3},{%4,%5,%6,%7},{%8,%9},{%0,%1,%2,%3};"
                 : "+f"(c[0]), "+f"(c[1]), "+f"(c[2]), "+f"(c[3])
                 : "r"(a[0]), "r"(a[1]), "r"(a[2]), "r"(a[3]), "r"(b0), "r"(b1));
}

__device__ __forceinline__ void hi_store(__half* dh, size_t off, float v0, float v1) {
    __half2 hp = __halves2half2(__float2half(v0), __float2half(v1));
    *(uint32_t*)(dh + off) = *(uint32_t*)&hp;
}
__device__ __forceinline__ uint32_t pack_h2(float v0, float v1) {
    __half2 hp = __halves2half2(__float2half(v0), __float2half(v1));
    return *(uint32_t*)&hp;
}

// ---------------------------------------------------------------------------
__global__ __launch_bounds__(256) void convert_x(const float* __restrict__ src)
{
    int i = blockIdx.x * 256 + threadIdx.x;
    float4 v = ((const float4*)src)[i];
    hi_store(g_xh, (size_t)i * 4,     v.x, v.y);
    hi_store(g_xh, (size_t)i * 4 + 2, v.z, v.w);
}

template<int W>
__global__ void transpose_w(const float* __restrict__ w)
{
    __half* th = (W == 0) ? g_wqh : g_wph;
    const int N = (W == 0) ? N_QKV : CC;
    __shared__ float ts[32][33];
    int n0 = blockIdx.x * 32, k0 = blockIdx.y * 32;
    int tx = threadIdx.x, ty = threadIdx.y;
    #pragma unroll
    for (int i = 0; i < 32; i += 8)
        ts[ty + i][tx] = w[(size_t)(k0 + ty + i) * N + n0 + tx];
    __syncthreads();
    #pragma unroll
    for (int i = 0; i < 32; i += 8)
        th[(size_t)(n0 + ty + i) * CC + k0 + tx] = __float2half(ts[tx][ty + i]);
}

// ---------------------------------------------------------------------------
// GEMM: C[128x128] = A[M,1024] @ B^T + bias. fp16 1-pass, fp32 accum.
// stage: Ah(10240) + Bh(10240) = 20480; 3 stages; one sync per K-iter.
// ---------------------------------------------------------------------------
#define GST 20480
#define GSMEM (3*GST)

template<int EPI>
__global__ __launch_bounds__(256, 2) void mma_gemm(const float* __restrict__ bias,
                                                   float* __restrict__ outp)
{
    const __half* Ah = (EPI == 0) ? g_xh : g_ah;
    const __half* Bh = (EPI == 0) ? g_wqh : g_wph;

    extern __shared__ char smc[];
    const uint32_t smb = smem_u32(smc);
    const int t = threadIdx.x, wid = t >> 5, l = t & 31;
    const int wm = wid >> 2, wn = wid & 3;
    const int n0 = blockIdx.x * 128, m0 = blockIdx.y * 128;

    float acc[4][4][4];
    #pragma unroll
    for (int i = 0; i < 4; i++)
        #pragma unroll
        for (int j = 0; j < 4; j++)
            #pragma unroll
            for (int k = 0; k < 4; k++) acc[i][j][k] = 0.f;

    auto issue = [&](int s) {
        const int koff = s * 32;
        const uint32_t sb = smb + (s % 3) * GST;
        // 256 threads x 1 iter covers 128 rows x 2 chunks per matrix? need
        // 128 rows x 64 half = 128x4 chunks of 16B = 512 ld per matrix.
        #pragma unroll
        for (int i = 0; i < 2; i++) {
            int c = 2 * t + i, row = c >> 2, q = c & 3;
            uint32_t so = (uint32_t)(row * 80 + q * 16);
            cpasync16(sb + so,         Ah + (size_t)(m0 + row) * CC + koff + q * 8);
            cpasync16(sb + 10240 + so, Bh + (size_t)(n0 + row) * CC + koff + q * 8);
        }
        CP_COMMIT();
    };

    issue(0);
    issue(1);
    for (int s = 0; s < 32; s++) {
        if (s < 30) CP_WAIT(1);
        else        CP_WAIT(0);
        __syncthreads();
        if (s + 2 < 32) issue(s + 2);
        const uint32_t sb = smb + (s % 3) * GST;
        #pragma unroll
        for (int ks = 0; ks < 2; ks++) {
            uint32_t ah[4][4];
            #pragma unroll
            for (int mt = 0; mt < 4; mt++) {
                uint32_t ad = sb + (uint32_t)((wm * 64 + mt * 16 + (l & 15)) * 80
                                              + ks * 32 + (l >> 4) * 16);
                ldsm4(ah[mt][0], ah[mt][1], ah[mt][2], ah[mt][3], ad);
            }
            uint32_t bh[4][2];
            #pragma unroll
            for (int j = 0; j < 2; j++) {
                uint32_t bd = sb + 10240
                    + (uint32_t)((wn * 32 + 16 * j + (l & 7) + ((l >> 4) & 1) * 8) * 80
                                 + ks * 32 + ((l >> 3) & 1) * 16);
                uint32_t r0, r1, r2, r3;
                ldsm4(r0, r1, r2, r3, bd);
                bh[2*j][0] = r0; bh[2*j][1] = r1; bh[2*j+1][0] = r2; bh[2*j+1][1] = r3;
            }
            #pragma unroll
            for (int mt = 0; mt < 4; mt++)
                #pragma unroll
                for (int nt = 0; nt < 4; nt++)
                    mma16816(acc[mt][nt], ah[mt], bh[nt][0], bh[nt][1]);
        }
    }

    #pragma unroll
    for (int mt = 0; mt < 4; mt++) {
        const int rA = m0 + wm * 64 + mt * 16 + (l >> 2);
        const int rB = rA + 8;
        #pragma unroll
        for (int nt = 0; nt < 4; nt++) {
            const int n = n0 + wn * 32 + nt * 8 + 2 * (l & 3);
            const float bi0 = bias[n], bi1 = bias[n + 1];
            float v0 = acc[mt][nt][0] + bi0, v1 = acc[mt][nt][1] + bi1;
            float v2 = acc[mt][nt][2] + bi0, v3 = acc[mt][nt][3] + bi1;
            if (EPI == 0) {
                const int which = n >> 10;
                const int h = (n & 1023) >> 6, d = n & 63;
                const int bA = rA >> 11, tA = rA & 2047;
                const int bB = rB >> 11, tB = rB & 2047;
                const size_t oA = (((size_t)(bA * NH + h)) * TT + tA) * HD + d;
                const size_t oB = (((size_t)(bB * NH + h)) * TT + tB) * HD + d;
                if (which == 0) {
                    hi_store(g_qh, oA, v0 * 0.125f, v1 * 0.125f);
                    hi_store(g_qh, oB, v2 * 0.125f, v3 * 0.125f);
                } else if (which == 1) {
                    hi_store(g_kh, oA, v0, v1);
                    hi_store(g_kh, oB, v2, v3);
                } else {
                    hi_store(g_vh, oA, v0, v1);
                    hi_store(g_vh, oB, v2, v3);
                }
            } else {
                *(float2*)&outp[(size_t)rA * CC + n] = make_float2(v0, v1);
                *(float2*)&outp[(size_t)rB * CC + n] = make_float2(v2, v3);
            }
        }
    }
}

// ---------------------------------------------------------------------------
// Flash attention, fp16 1-pass. 256 thr / 8 warps, 128-row q tile, 64-col KV.
// smem: Qh@0 (18432) | 3 KV stages @18432 + stg*18432 (Kh, Vh@+9216)
// ---------------------------------------------------------------------------
#define FQ_SZ 18432
#define FKV_OFF 18432
#define FKV_ST 18432
#define FLASH_SMEM (FKV_OFF + 3*FKV_ST)   // 73728

__global__ __launch_bounds__(256, 2) void flash_mma()
{
    extern __shared__ char smc[];
    const uint32_t smb = smem_u32(smc);
    const int t = threadIdx.x, w = t >> 5, l = t & 31;
    const int qt = (int)gridDim.x - 1 - (int)blockIdx.x;   // heavy tiles first
    const int h = blockIdx.y, b = blockIdx.z;
    const size_t hoff = ((size_t)(b * NH + h)) * TT * HD;
    const int q0 = qt * 128;
    const int nk = 2 * qt + 2;            // 64-col KV tiles

    auto kvload = [&](int kt) {
        const uint32_t sb = smb + FKV_OFF + (kt % 3) * FKV_ST;
        const int k0 = kt * 64;
        #pragma unroll
        for (int i = 0; i < 2; i++) {
            int c = t + i * 256, row = c >> 3, q = c & 7;
            uint32_t so = (uint32_t)(row * 144 + q * 16);
            size_t g = hoff + (size_t)(k0 + row) * HD + q * 8;
            cpasync16(sb + so,        g_kh + g);
            cpasync16(sb + 9216 + so, g_vh + g);
        }
        CP_COMMIT();
    };

    #pragma unroll
    for (int i = 0; i < 2; i++) {
        int c = t + i * 256, row = c >> 2, q = c & 3;   // 128 rows x 4 chunks
        uint32_t so = (uint32_t)(row * 144 + q * 16) + (uint32_t)((q >> 2) * 0);
        // row*144 + q*16 covers 64B of the 128B row; need 8 chunks per row:
        (void)so;
    }
    // Q: 128 rows x 128B = 1024 chunks of 16B; 256 thr x 4
    #pragma unroll
    for (int i = 0; i < 4; i++) {
        int c = t + i * 256, row = c >> 3, q = c & 7;
        uint32_t so = (uint32_t)(row * 144 + q * 16);
        cpasync16(smb + so, g_qh + hoff + (size_t)(q0 + row) * HD + q * 8);
    }
    kvload(0);
    kvload(1);

    float mA = -1e30f, mB = -1e30f, lA = 0.f, lB = 0.f;
    float o[8][4];
    #pragma unroll
    for (int j = 0; j < 8; j++)
        #pragma unroll
        for (int k = 0; k < 4; k++) o[j][k] = 0.f;

    uint32_t qh[4][4];

    for (int kt = 0; kt < nk; kt++) {
        if (kt < nk - 1) CP_WAIT(1);
        else             CP_WAIT(0);
        __syncthreads();
        if (kt + 2 < nk) kvload(kt + 2);
        if (kt == 0) {
            #pragma unroll
            for (int ks = 0; ks < 4; ks++) {
                uint32_t ad = smb + (uint32_t)((w * 16 + (l & 15)) * 144
                                               + ks * 32 + (l >> 4) * 16);
                ldsm4(qh[ks][0], qh[ks][1], qh[ks][2], qh[ks][3], ad);
            }
        }
        const uint32_t sb = smb + FKV_OFF + (kt % 3) * FKV_ST;

        // S = Q K^T (1-pass)
        float s[8][4];
        #pragma unroll
        for (int j = 0; j < 8; j++)
            #pragma unroll
            for (int k = 0; k < 4; k++) s[j][k] = 0.f;
        #pragma unroll
        for (int ks = 0; ks < 4; ks++) {
            #pragma unroll
            for (int j = 0; j < 4; j++) {
                uint32_t kd = sb + (uint32_t)((16 * j + (l & 7) + ((l >> 4) & 1) * 8) * 144
                                              + ks * 32 + ((l >> 3) & 1) * 16);
                uint32_t r0, r1, r2, r3;
                ldsm4(r0, r1, r2, r3, kd);
                mma16816(s[2*j],   qh[ks], r0, r1);
                mma16816(s[2*j+1], qh[ks], r2, r3);
            }
        }

        const int rA = q0 + w * 16 + (l >> 2), rB = rA + 8;
        if (kt >= 2 * qt) {
            const int cb = 2 * (l & 3);
            #pragma unroll
            for (int j = 0; j < 8; j++) {
                int cg = kt * 64 + 8 * j + cb;
                if (cg     > rA) s[j][0] = -1e30f;
                if (cg + 1 > rA) s[j][1] = -1e30f;
                if (cg     > rB) s[j][2] = -1e30f;
                if (cg + 1 > rB) s[j][3] = -1e30f;
            }
        }

        // online softmax
        float mxA = -1e30f, mxB = -1e30f;
        #pragma unroll
        for (int j = 0; j < 8; j++) {
            mxA = fmaxf(mxA, fmaxf(s[j][0], s[j][1]));
            mxB = fmaxf(mxB, fmaxf(s[j][2], s[j][3]));
        }
        mxA = fmaxf(mxA, __shfl_xor_sync(0xffffffffu, mxA, 1));
        mxA = fmaxf(mxA, __shfl_xor_sync(0xffffffffu, mxA, 2));
        mxB = fmaxf(mxB, __shfl_xor_sync(0xffffffffu, mxB, 1));
        mxB = fmaxf(mxB, __shfl_xor_sync(0xffffffffu, mxB, 2));
        const float nmA = fmaxf(mA, mxA), nmB = fmaxf(mB, mxB);
        const float aA = __expf(mA - nmA), aB = __expf(mB - nmB);
        mA = nmA; mB = nmB;
        float suA = 0.f, suB = 0.f;
        #pragma unroll
        for (int j = 0; j < 8; j++) {
            s[j][0] = __expf(s[j][0] - mA);
            s[j][1] = __expf(s[j][1] - mA);
            s[j][2] = __expf(s[j][2] - mB);
            s[j][3] = __expf(s[j][3] - mB);
            suA += s[j][0] + s[j][1];
            suB += s[j][2] + s[j][3];
        }
        suA += __shfl_xor_sync(0xffffffffu, suA, 1);
        suA += __shfl_xor_sync(0xffffffffu, suA, 2);
        suB += __shfl_xor_sync(0xffffffffu, suB, 1);
        suB += __shfl_xor_sync(0xffffffffu, suB, 2);
        lA = lA * aA + suA;
        lB = lB * aB + suB;
        #pragma unroll
        for (int j = 0; j < 8; j++) {
            o[j][0] *= aA; o[j][1] *= aA; o[j][2] *= aB; o[j][3] *= aB;
        }

        // O += P V (1-pass; V via ldmatrix.trans)
        #pragma unroll
        for (int ks = 0; ks < 4; ks++) {
            uint32_t pa[4];
            pa[0] = pack_h2(s[2*ks][0],   s[2*ks][1]);
            pa[1] = pack_h2(s[2*ks][2],   s[2*ks][3]);
            pa[2] = pack_h2(s[2*ks+1][0], s[2*ks+1][1]);
            pa[3] = pack_h2(s[2*ks+1][2], s[2*ks+1][3]);
            #pragma unroll
            for (int j = 0; j < 4; j++) {
                uint32_t vd = sb + 9216
                    + (uint32_t)((ks * 16 + (l & 7) + ((l >> 3) & 1) * 8) * 144
                                 + 32 * j + ((l >> 4) & 1) * 16);
                uint32_t r0, r1, r2, r3;
                ldsm4t(r0, r1, r2, r3, vd);
                mma16816(o[2*j],   pa, r0, r1);
                mma16816(o[2*j+1], pa, r2, r3);
            }
        }
    }

    const float iA = 1.f / lA, iB = 1.f / lB;
    const int rA = q0 + w * 16 + (l >> 2), rB = rA + 8;
    const size_t baseA = ((size_t)(b * TT + rA)) * CC + h * HD;
    const size_t baseB = ((size_t)(b * TT + rB)) * CC + h * HD;
    #pragma unroll
    for (int j = 0; j < 8; j++) {
        const int d = 8 * j + 2 * (l & 3);
        hi_store(g_ah, baseA + d, o[j][0] * iA, o[j][1] * iA);
        hi_store(g_ah, baseB + d, o[j][2] * iB, o[j][3] * iB);
    }
}

// ---------------------------------------------------------------------------
extern "C" void kernel_launch(void* const* d_in, const int* in_sizes, int n_in,
                              void* d_out, int out_size)
{
    const float* x      = (const float*)d_in[0];
    const float* w_attn = (const float*)d_in[1];
    const float* b_attn = (const float*)d_in[2];
    const float* w_proj = (const float*)d_in[3];
    const float* b_proj = (const float*)d_in[4];
    float* out = (float*)d_out;

    cudaFuncSetAttribute(mma_gemm<0>, cudaFuncAttributeMaxDynamicSharedMemorySize, GSMEM);
    cudaFuncSetAttribute(mma_gemm<1>, cudaFuncAttributeMaxDynamicSharedMemorySize, GSMEM);
    cudaFuncSetAttribute(flash_mma, cudaFuncAttributeMaxDynamicSharedMemorySize, FLASH_SMEM);

    convert_x<<<M1 * CC / 1024, 256>>>(x);
    transpose_w<0><<<dim3(N_QKV / 32, CC / 32), dim3(32, 8)>>>(w_attn);
    transpose_w<1><<<dim3(CC / 32, CC / 32), dim3(32, 8)>>>(w_proj);

    mma_gemm<0><<<dim3(N_QKV / 128, M1 / 128), 256, GSMEM>>>(b_attn, nullptr);
    flash_mma<<<dim3(TT / 128, NH, BB), 256, FLASH_SMEM>>>();
    mma_gemm<1><<<dim3(CC / 128, M1 / 128), 256, GSMEM>>>(b_proj, out);
}